// round 16
// baseline (speedup 1.0000x reference)
#include <cuda_runtime.h>
#include <cuda_bf16.h>
#include <cstdint>
#include <mma.h>

using namespace nvcuda;

#define DMODEL 1024
#define NHEAD  16
#define DKH    64
#define DFF    4096
#define BATCH  4
#define SEQ    2048
#define MTOK   (BATCH * SEQ)

// ---------------- scratch (device globals; no allocation allowed) -------------
__device__ float g_x1[MTOK * DMODEL];
__device__ float g_x2[MTOK * DMODEL];
__device__ float g_t[MTOK * DMODEL];
__device__ __nv_bfloat16 g_q16[MTOK * DMODEL];
__device__ __nv_bfloat16 g_k16[MTOK * DMODEL];
__device__ __nv_bfloat16 g_v16[MTOK * DMODEL];
__device__ __nv_bfloat16 g_a16[2 * MTOK * DMODEL];  // two activation slots
__device__ __nv_bfloat16 g_h16[MTOK * DFF];         // FF hidden (bf16)
__device__ __nv_bfloat16 g_w16[DMODEL * DFF];       // weight scratch

// ---------------- fp32 -> bf16 conversion ------------------------------------
__global__ __launch_bounds__(256) void f2bf_kernel(
    const float* __restrict__ in, __nv_bfloat16* __restrict__ out, int n4)
{
    int i = blockIdx.x * blockDim.x + threadIdx.x;
    if (i < n4) {
        float4 v = reinterpret_cast<const float4*>(in)[i];
        __nv_bfloat162 a = __floats2bfloat162_rn(v.x, v.y);
        __nv_bfloat162 b = __floats2bfloat162_rn(v.z, v.w);
        uint2 u;
        u.x = *reinterpret_cast<unsigned*>(&a);
        u.y = *reinterpret_cast<unsigned*>(&b);
        reinterpret_cast<uint2*>(out)[i] = u;
    }
}

// ---------------- cp.async helper ---------------------------------------------
__device__ __forceinline__ void cp16(void* dst, const void* src) {
    unsigned d = (unsigned)__cvta_generic_to_shared(dst);
    asm volatile("cp.async.cg.shared.global [%0], [%1], 16;\n" :: "r"(d), "l"(src));
}

// ---------------- bf16 WMMA GEMM -----------------------------------------------
// BM=256, BN=128, BK=64; 8 warps, warp tile 64x64. 3-stage cp.async ring.
// OUT16=0: fp32 out to Cf.  OUT16=1: bf16 out to C16 (smem staging).
template <int RELU, int OUT16>
__global__ __launch_bounds__(256) void bf16_gemm_bias(
    const __nv_bfloat16* __restrict__ A, const __nv_bfloat16* __restrict__ W,
    const float* __restrict__ bias, float* __restrict__ Cf,
    __nv_bfloat16* __restrict__ C16, int M, int N, int K)
{
    constexpr int BM = 256, BN = 128, BK = 64;
    constexpr int LDA = 72;
    constexpr int LDB = 136;
    constexpr int ASTG = BM * LDA;
    constexpr int BSTG = BK * LDB;
    extern __shared__ __nv_bfloat16 gs[];
    __nv_bfloat16* const Asm = gs;
    __nv_bfloat16* const Bsm = gs + 3 * ASTG;

    const int tid = threadIdx.x;
    const int wid = tid >> 5;
    const int wm  = wid >> 1;
    const int wn  = wid & 1;
    const int bm  = blockIdx.y * BM;
    const int bn  = blockIdx.x * BN;

    wmma::fragment<wmma::accumulator, 16, 16, 16, float> acc[4][4];

    {
        float* fs = reinterpret_cast<float*>(gs);
        int rr = tid >> 5;
        int n4 = (tid & 31) << 2;
        float4 bv = *reinterpret_cast<const float4*>(bias + bn + n4);
        *reinterpret_cast<float4*>(&fs[rr * 136 + n4])       = bv;
        *reinterpret_cast<float4*>(&fs[(rr + 8) * 136 + n4]) = bv;
        __syncthreads();
        #pragma unroll
        for (int fc = 0; fc < 4; fc++) {
            wmma::load_matrix_sync(acc[0][fc], &fs[wn * 64 + fc * 16], 136,
                                   wmma::mem_row_major);
            #pragma unroll
            for (int fr = 1; fr < 4; fr++)
                #pragma unroll
                for (int e = 0; e < acc[0][fc].num_elements; e++)
                    acc[fr][fc].x[e] = acc[0][fc].x[e];
        }
        __syncthreads();
    }

    const __nv_bfloat16* const Ab = A + (size_t)bm * K;
    const __nv_bfloat16* const Wb = W + bn;

#define GISS(st, k0)                                                             \
    do {                                                                         \
        __nv_bfloat16* as = Asm + (st) * ASTG;                                   \
        __nv_bfloat16* bs = Bsm + (st) * BSTG;                                   \
        _Pragma("unroll")                                                        \
        for (int i = 0; i < 8; i++) {                                            \
            int idx = tid + i * 256;                                             \
            int r = idx >> 3, c8 = (idx & 7) * 8;                                \
            cp16(&as[r * LDA + c8], Ab + (size_t)r * K + (k0) + c8);             \
        }                                                                        \
        _Pragma("unroll")                                                        \
        for (int i = 0; i < 4; i++) {                                            \
            int idx = tid + i * 256;                                             \
            int r = idx >> 4, c8 = (idx & 15) * 8;                               \
            cp16(&bs[r * LDB + c8], Wb + (size_t)((k0) + r) * N + c8);           \
        }                                                                        \
        asm volatile("cp.async.commit_group;\n");                                \
    } while (0)

    const int NS = K / BK;
    GISS(0, 0);
    if (NS > 1) GISS(1, BK);

    int st = 0;
    for (int s = 0; s < NS; s++) {
        if (s + 1 < NS) asm volatile("cp.async.wait_group 1;\n");
        else            asm volatile("cp.async.wait_group 0;\n");
        __syncthreads();

        const __nv_bfloat16* as = Asm + st * ASTG;
        const __nv_bfloat16* bs = Bsm + st * BSTG;
        #pragma unroll
        for (int kk = 0; kk < BK; kk += 16) {
            wmma::fragment<wmma::matrix_a, 16, 16, 16, __nv_bfloat16,
                           wmma::row_major> af[4];
            wmma::fragment<wmma::matrix_b, 16, 16, 16, __nv_bfloat16,
                           wmma::row_major> bf[4];
            #pragma unroll
            for (int fr = 0; fr < 4; fr++)
                wmma::load_matrix_sync(af[fr], &as[(wm * 64 + fr * 16) * LDA + kk], LDA);
            #pragma unroll
            for (int fc = 0; fc < 4; fc++)
                wmma::load_matrix_sync(bf[fc], &bs[kk * LDB + wn * 64 + fc * 16], LDB);
            #pragma unroll
            for (int fr = 0; fr < 4; fr++)
                #pragma unroll
                for (int fc = 0; fc < 4; fc++)
                    wmma::mma_sync(acc[fr][fc], af[fr], bf[fc], acc[fr][fc]);
        }

        if (s + 2 < NS) {
            int nst = (st + 2) % 3;
            GISS(nst, (s + 2) * BK);
        }
        st = (st + 1) % 3;
    }
#undef GISS

    if (OUT16) {
        __syncthreads();
        float* stg = reinterpret_cast<float*>(gs) + wid * 256;
        const int lane = tid & 31;
        const int row  = lane >> 1;
        const int col  = (lane & 1) * 8;
        #pragma unroll
        for (int fr = 0; fr < 4; fr++)
            #pragma unroll
            for (int fc = 0; fc < 4; fc++) {
                if (RELU) {
                    #pragma unroll
                    for (int e = 0; e < acc[fr][fc].num_elements; e++)
                        acc[fr][fc].x[e] = fmaxf(acc[fr][fc].x[e], 0.0f);
                }
                wmma::store_matrix_sync(stg, acc[fr][fc], 16, wmma::mem_row_major);
                __syncwarp();
                float4 a  = *reinterpret_cast<float4*>(&stg[row * 16 + col]);
                float4 b4 = *reinterpret_cast<float4*>(&stg[row * 16 + col + 4]);
                __nv_bfloat162 p0 = __floats2bfloat162_rn(a.x,  a.y);
                __nv_bfloat162 p1 = __floats2bfloat162_rn(a.z,  a.w);
                __nv_bfloat162 p2 = __floats2bfloat162_rn(b4.x, b4.y);
                __nv_bfloat162 p3 = __floats2bfloat162_rn(b4.z, b4.w);
                uint4 u;
                u.x = *reinterpret_cast<unsigned*>(&p0);
                u.y = *reinterpret_cast<unsigned*>(&p1);
                u.z = *reinterpret_cast<unsigned*>(&p2);
                u.w = *reinterpret_cast<unsigned*>(&p3);
                *reinterpret_cast<uint4*>(
                    C16 + (size_t)(bm + wm * 64 + fr * 16 + row) * N
                        + bn + wn * 64 + fc * 16 + col) = u;
                __syncwarp();
            }
    } else {
        #pragma unroll
        for (int fr = 0; fr < 4; fr++)
            #pragma unroll
            for (int fc = 0; fc < 4; fc++) {
                if (RELU) {
                    #pragma unroll
                    for (int e = 0; e < acc[fr][fc].num_elements; e++)
                        acc[fr][fc].x[e] = fmaxf(acc[fr][fc].x[e], 0.0f);
                }
                float* cp = Cf + (size_t)(bm + wm * 64 + fr * 16) * N
                               + bn + wn * 64 + fc * 16;
                wmma::store_matrix_sync(cp, acc[fr][fc], N, wmma::mem_row_major);
            }
    }
}

#define GSMEM_BYTES ((3 * (256 * 72) + 3 * (64 * 136)) * 2)   // 162816

// ============== bf16 tensor-core flash attention (m16n8k16, dk=64) ============
// KV tile 128 (amortizes softmax/barrier fixed costs). K staged row-major via
// cp.async double buffer; V register-prefetched and stored transposed (d-major);
// P stored bf16x2. Strides: K rows 72 bf16 (36 words), Vt/P rows 136 bf16
// (68 words) — both ≡ 4 mod 32 words per row: conflict-free fragment loads.
#define HLDK 72
#define HLDV 136
#define HLDP 136
#define HKSTG (128 * HLDK)                 // 9216 bf16 per K stage
#define HVT_OFF (2 * HKSTG)                // 18432
#define HVSTG (64 * HLDV)                  // 8704 bf16 per Vt stage
#define HPS_OFF (HVT_OFF + 2 * HVSTG)      // 35840
#define HSMEM_H (HPS_OFF + 128 * HLDP)     // 53248 bf16
#define HSMEM_BYTES (HSMEM_H * 2)          // 106496 B

__device__ __forceinline__ void mma_bf16(float* d, const unsigned* a,
                                         const unsigned* b) {
    asm volatile(
        "mma.sync.aligned.m16n8k16.row.col.f32.bf16.bf16.f32 "
        "{%0,%1,%2,%3}, {%4,%5,%6,%7}, {%8,%9}, {%0,%1,%2,%3};\n"
        : "+f"(d[0]), "+f"(d[1]), "+f"(d[2]), "+f"(d[3])
        : "r"(a[0]), "r"(a[1]), "r"(a[2]), "r"(a[3]), "r"(b[0]), "r"(b[1]));
}

__global__ __launch_bounds__(256) void flash_attn_bf16(
    const __nv_bfloat16* __restrict__ Qg, const __nv_bfloat16* __restrict__ Kg,
    const __nv_bfloat16* __restrict__ Vg, __nv_bfloat16* __restrict__ Og16,
    int Sq, int Skv)
{
    extern __shared__ __nv_bfloat16 hsm[];
    unsigned* smw = reinterpret_cast<unsigned*>(hsm);

    const int tid  = threadIdx.x;
    const int lane = tid & 31;
    const int w    = tid >> 5;
    const int q0   = blockIdx.x * 128;
    const int h    = blockIdx.y;
    const int b    = blockIdx.z;
    const int r0   = lane >> 2;
    const int cq   = lane & 3;

    // K loader: 128 rows x 64 cols = 1024 x 16B chunks, 4 per thread
#define KISS(st, kvoff)                                                          \
    do {                                                                         \
        __nv_bfloat16* kb = hsm + (st) * HKSTG;                                  \
        _Pragma("unroll")                                                        \
        for (int i = 0; i < 4; i++) {                                            \
            int idx = tid + i * 256;                                             \
            int r = idx >> 3, o8 = (idx & 7) * 8;                                \
            cp16(&kb[r * HLDK + o8],                                             \
                 Kg + (size_t)(b * Skv + (kvoff) + r) * DMODEL + h * DKH + o8);  \
        }                                                                        \
        asm volatile("cp.async.commit_group;\n");                                \
    } while (0)

    // V prefetch: thread owns kv-row vc (0..127), d-cols vd..vd+31
    const int vc = tid & 127;
    const int vd = (tid >> 7) * 32;
    uint4 vr[4];
#define VLOAD(kvoff)                                                             \
    do {                                                                         \
        const uint4* vp = reinterpret_cast<const uint4*>(                        \
            Vg + (size_t)(b * Skv + (kvoff) + vc) * DMODEL + h * DKH + vd);      \
        vr[0] = vp[0]; vr[1] = vp[1]; vr[2] = vp[2]; vr[3] = vp[3];              \
    } while (0)

    KISS(0, 0);
    VLOAD(0);

    // Q fragments (bf16, scale 1/8 folded in: exact exponent shift)
    unsigned qa[4][4];
    {
        const __nv_bfloat162 s2 = __float2bfloat162_rn(0.125f);
        const __nv_bfloat16* Qb = Qg + (size_t)(b * Sq + q0 + w * 16) * DMODEL + h * DKH;
        #pragma unroll
        for (int ds = 0; ds < 4; ds++) {
            #pragma unroll
            for (int p = 0; p < 4; p++) {
                int rr = (p & 1) ? r0 + 8 : r0;
                int cc = ds * 16 + 2 * cq + ((p & 2) ? 8 : 0);
                __nv_bfloat162 x = *reinterpret_cast<const __nv_bfloat162*>(
                    Qb + (size_t)rr * DMODEL + cc);
                x = __hmul2(x, s2);
                qa[ds][p] = *reinterpret_cast<unsigned*>(&x);
            }
        }
    }

    float m0 = -1e30f, m1 = -1e30f, l0 = 0.0f, l1 = 0.0f;
    float o[8][4];
    #pragma unroll
    for (int nt = 0; nt < 8; nt++)
        o[nt][0] = o[nt][1] = o[nt][2] = o[nt][3] = 0.0f;

    unsigned* const pw = smw + (HPS_OFF >> 1) + (w * 16) * (HLDP >> 1);
    const int NS = Skv / 128;

    for (int s = 0; s < NS; s++) {
        // store V(s) transposed into Vt[s&1]
        {
            __nv_bfloat16* vt = hsm + HVT_OFF + (s & 1) * HVSTG;
            __nv_bfloat16 tmp[32];
            *reinterpret_cast<uint4*>(tmp)      = vr[0];
            *reinterpret_cast<uint4*>(tmp + 8)  = vr[1];
            *reinterpret_cast<uint4*>(tmp + 16) = vr[2];
            *reinterpret_cast<uint4*>(tmp + 24) = vr[3];
            #pragma unroll
            for (int j = 0; j < 32; j++)
                vt[(vd + j) * HLDV + vc] = tmp[j];
        }
        if (s + 1 < NS) {
            __syncthreads();            // K buf (s+1)&1 free; Vt[s&1] stores done
            KISS((s + 1) & 1, (s + 1) * 128);
            VLOAD((s + 1) * 128);
            asm volatile("cp.async.wait_group 1;\n");
        } else {
            asm volatile("cp.async.wait_group 0;\n");
        }
        __syncthreads();                // K(s), Vt[s&1] visible

        const unsigned* kw  = smw + (((s & 1) * HKSTG) >> 1);
        const unsigned* vtw = smw + ((HVT_OFF + (s & 1) * HVSTG) >> 1);

        // ---- S = (Q/8) K^T : 4 k16-steps x 16 n-tiles ----
        float sc[16][4];
        #pragma unroll
        for (int nt = 0; nt < 16; nt++)
            sc[nt][0] = sc[nt][1] = sc[nt][2] = sc[nt][3] = 0.0f;

        #pragma unroll
        for (int ds = 0; ds < 4; ds++) {
            #pragma unroll
            for (int nt = 0; nt < 16; nt++) {
                const unsigned* kp = kw + (nt * 8 + r0) * 36 + ds * 8 + cq;
                unsigned bb[2] = { kp[0], kp[4] };
                mma_bf16(sc[nt], qa[ds], bb);
            }
        }

        // ---- online softmax (fixed costs amortized over 128 cols) ----
        float mx0 = sc[0][0], mx1 = sc[0][2];
        #pragma unroll
        for (int nt = 0; nt < 16; nt++) {
            mx0 = fmaxf(mx0, fmaxf(sc[nt][0], sc[nt][1]));
            mx1 = fmaxf(mx1, fmaxf(sc[nt][2], sc[nt][3]));
        }
        mx0 = fmaxf(mx0, __shfl_xor_sync(0xffffffffu, mx0, 1));
        mx0 = fmaxf(mx0, __shfl_xor_sync(0xffffffffu, mx0, 2));
        mx1 = fmaxf(mx1, __shfl_xor_sync(0xffffffffu, mx1, 1));
        mx1 = fmaxf(mx1, __shfl_xor_sync(0xffffffffu, mx1, 2));

        float mn0 = fmaxf(m0, mx0), mn1 = fmaxf(m1, mx1);
        float al0 = __expf(m0 - mn0), al1 = __expf(m1 - mn1);
        m0 = mn0; m1 = mn1;

        float sum0 = 0.0f, sum1 = 0.0f;
        #pragma unroll
        for (int nt = 0; nt < 16; nt++) {
            sc[nt][0] = __expf(sc[nt][0] - mn0);
            sc[nt][1] = __expf(sc[nt][1] - mn0);
            sc[nt][2] = __expf(sc[nt][2] - mn1);
            sc[nt][3] = __expf(sc[nt][3] - mn1);
            sum0 += sc[nt][0] + sc[nt][1];
            sum1 += sc[nt][2] + sc[nt][3];
        }
        sum0 += __shfl_xor_sync(0xffffffffu, sum0, 1);
        sum0 += __shfl_xor_sync(0xffffffffu, sum0, 2);
        sum1 += __shfl_xor_sync(0xffffffffu, sum1, 1);
        sum1 += __shfl_xor_sync(0xffffffffu, sum1, 2);
        l0 = l0 * al0 + sum0;
        l1 = l1 * al1 + sum1;

        // ---- rescale O; write P as bf16x2 to warp-private strip ----
        #pragma unroll
        for (int nt = 0; nt < 8; nt++) {
            o[nt][0] *= al0; o[nt][1] *= al0;
            o[nt][2] *= al1; o[nt][3] *= al1;
        }
        #pragma unroll
        for (int nt = 0; nt < 16; nt++) {
            __nv_bfloat162 p01 = __floats2bfloat162_rn(sc[nt][0], sc[nt][1]);
            __nv_bfloat162 p23 = __floats2bfloat162_rn(sc[nt][2], sc[nt][3]);
            pw[r0 * 68 + nt * 4 + cq]       = *reinterpret_cast<unsigned*>(&p01);
            pw[(r0 + 8) * 68 + nt * 4 + cq] = *reinterpret_cast<unsigned*>(&p23);
        }
        __syncwarp();

        // ---- O += P @ V : 8 k16-steps x 8 n-tiles ----
        #pragma unroll
        for (int kk = 0; kk < 8; kk++) {
            unsigned pa[4];
            pa[0] = pw[r0 * 68 + kk * 8 + cq];
            pa[1] = pw[(r0 + 8) * 68 + kk * 8 + cq];
            pa[2] = pw[r0 * 68 + kk * 8 + cq + 4];
            pa[3] = pw[(r0 + 8) * 68 + kk * 8 + cq + 4];
            #pragma unroll
            for (int nt = 0; nt < 8; nt++) {
                const unsigned* vp = vtw + (nt * 8 + r0) * 68 + kk * 8 + cq;
                unsigned bb[2] = { vp[0], vp[4] };
                mma_bf16(o[nt], pa, bb);
            }
        }
    }
#undef KISS
#undef VLOAD

    // ---- epilogue: O / l, write bf16 ----
    const float i0 = 1.0f / l0, i1 = 1.0f / l1;
    __nv_bfloat16* Ob = Og16 + (size_t)(b * Sq + q0 + w * 16) * DMODEL + h * DKH;
    #pragma unroll
    for (int nt = 0; nt < 8; nt++) {
        __nv_bfloat162 v0 = __floats2bfloat162_rn(o[nt][0] * i0, o[nt][1] * i0);
        __nv_bfloat162 v1 = __floats2bfloat162_rn(o[nt][2] * i1, o[nt][3] * i1);
        *reinterpret_cast<unsigned*>(Ob + (size_t)r0 * DMODEL + nt * 8 + 2 * cq) =
            *reinterpret_cast<unsigned*>(&v0);
        *reinterpret_cast<unsigned*>(Ob + (size_t)(r0 + 8) * DMODEL + nt * 8 + 2 * cq) =
            *reinterpret_cast<unsigned*>(&v1);
    }
}

// ---------------- out = LayerNorm(a + c) * g + b  (+ optional bf16 copy) ------
__global__ __launch_bounds__(256) void add_ln_kernel(
    const float* __restrict__ a, const float* __restrict__ cadd,
    const float* __restrict__ g, const float* __restrict__ be,
    float* __restrict__ out, __nv_bfloat16* __restrict__ out16)
{
    __shared__ float red[16];
    const int row = blockIdx.x;
    const int tid = threadIdx.x;
    const size_t base = (size_t)row * DMODEL + tid * 4;

    float4 av = *reinterpret_cast<const float4*>(a + base);
    float4 cv = *reinterpret_cast<const float4*>(cadd + base);
    float x0 = av.x + cv.x, x1 = av.y + cv.y;
    float x2 = av.z + cv.z, x3 = av.w + cv.w;

    float s  = x0 + x1 + x2 + x3;
    float ss = x0 * x0 + x1 * x1 + x2 * x2 + x3 * x3;
    #pragma unroll
    for (int off = 16; off; off >>= 1) {
        s  += __shfl_xor_sync(0xffffffffu, s,  off);
        ss += __shfl_xor_sync(0xffffffffu, ss, off);
    }
    if ((tid & 31) == 0) { red[tid >> 5] = s; red[8 + (tid >> 5)] = ss; }
    __syncthreads();
    float ts = 0.0f, tss = 0.0f;
    #pragma unroll
    for (int i = 0; i < 8; i++) { ts += red[i]; tss += red[8 + i]; }

    const float mu  = ts * (1.0f / DMODEL);
    const float var = tss * (1.0f / DMODEL) - mu * mu;
    const float inv = rsqrtf(var + 1e-5f);

    float4 gv = *reinterpret_cast<const float4*>(g  + tid * 4);
    float4 bv = *reinterpret_cast<const float4*>(be + tid * 4);
    float4 ov;
    ov.x = (x0 - mu) * inv * gv.x + bv.x;
    ov.y = (x1 - mu) * inv * gv.y + bv.y;
    ov.z = (x2 - mu) * inv * gv.z + bv.z;
    ov.w = (x3 - mu) * inv * gv.w + bv.w;
    *reinterpret_cast<float4*>(out + base) = ov;

    if (out16) {
        __nv_bfloat162 p0 = __floats2bfloat162_rn(ov.x, ov.y);
        __nv_bfloat162 p1 = __floats2bfloat162_rn(ov.z, ov.w);
        uint2 u;
        u.x = *reinterpret_cast<unsigned*>(&p0);
        u.y = *reinterpret_cast<unsigned*>(&p1);
        *reinterpret_cast<uint2*>(out16 + base) = u;
    }
}

// ------------------------------- host driver ----------------------------------
static inline void conv_f2bf(const float* in, __nv_bfloat16* out, int n) {
    int n4 = n >> 2;
    f2bf_kernel<<<(n4 + 255) / 256, 256>>>(in, out, n4);
}

static inline void launch_gemm16(const __nv_bfloat16* A, const __nv_bfloat16* W,
                                 const float* B, float* Cf, int M, int N, int K)
{
    dim3 grid(N / 128, M / 256), blk(256);
    bf16_gemm_bias<0, 0><<<grid, blk, GSMEM_BYTES>>>(A, W, B, Cf, nullptr, M, N, K);
}

static inline void launch_gemm16_bf16out(
    const __nv_bfloat16* A, const __nv_bfloat16* W,
    const float* B, __nv_bfloat16* C16, int M, int N, int K)
{
    dim3 grid(N / 128, M / 256), blk(256);
    bf16_gemm_bias<0, 1><<<grid, blk, GSMEM_BYTES>>>(A, W, B, nullptr, C16, M, N, K);
}

static inline void launch_gemm16_relu_bf16out(
    const __nv_bfloat16* A, const __nv_bfloat16* W,
    const float* B, __nv_bfloat16* C16, int M, int N, int K)
{
    dim3 grid(N / 128, M / 256), blk(256);
    bf16_gemm_bias<1, 1><<<grid, blk, GSMEM_BYTES>>>(A, W, B, nullptr, C16, M, N, K);
}

extern "C" void kernel_launch(void* const* d_in, const int* in_sizes, int n_in,
                              void* d_out, int out_size)
{
    const float* src   = (const float*)d_in[0];
    const float* tgt   = (const float*)d_in[1];
    const float* sa_wq = (const float*)d_in[2];
    const float* sa_bq = (const float*)d_in[3];
    const float* sa_wk = (const float*)d_in[4];
    const float* sa_bk = (const float*)d_in[5];
    const float* sa_wv = (const float*)d_in[6];
    const float* sa_bv = (const float*)d_in[7];
    const float* sa_wo = (const float*)d_in[8];
    const float* sa_bo = (const float*)d_in[9];
    const float* ca_wq = (const float*)d_in[10];
    const float* ca_bq = (const float*)d_in[11];
    const float* ca_wk = (const float*)d_in[12];
    const float* ca_bk = (const float*)d_in[13];
    const float* ca_wv = (const float*)d_in[14];
    const float* ca_bv = (const float*)d_in[15];
    const float* ca_wo = (const float*)d_in[16];
    const float* ca_bo = (const float*)d_in[17];
    const float* ff_w1 = (const float*)d_in[18];
    const float* ff_b1 = (const float*)d_in[19];
    const float* ff_w2 = (const float*)d_in[20];
    const float* ff_b2 = (const float*)d_in[21];
    const float* ln1_g = (const float*)d_in[22];
    const float* ln1_b = (const float*)d_in[23];
    const float* ln2_g = (const float*)d_in[24];
    const float* ln2_b = (const float*)d_in[25];
    const float* ln3_g = (const float*)d_in[26];
    const float* ln3_b = (const float*)d_in[27];
    float* out = (float*)d_out;

    float *x1, *x2, *t;
    __nv_bfloat16 *q16, *k16, *v16, *a16, *h16, *w16;
    cudaGetSymbolAddress((void**)&x1,  g_x1);
    cudaGetSymbolAddress((void**)&x2,  g_x2);
    cudaGetSymbolAddress((void**)&t,   g_t);
    cudaGetSymbolAddress((void**)&q16, g_q16);
    cudaGetSymbolAddress((void**)&k16, g_k16);
    cudaGetSymbolAddress((void**)&v16, g_v16);
    cudaGetSymbolAddress((void**)&a16, g_a16);
    cudaGetSymbolAddress((void**)&h16, g_h16);
    cudaGetSymbolAddress((void**)&w16, g_w16);

    const int NMM = MTOK * DMODEL;
    const int NW  = DMODEL * DMODEL;
    __nv_bfloat16* A0 = a16;
    __nv_bfloat16* A1 = a16 + NMM;

    cudaFuncSetAttribute(flash_attn_bf16,
                         cudaFuncAttributeMaxDynamicSharedMemorySize, HSMEM_BYTES);
    cudaFuncSetAttribute(bf16_gemm_bias<0, 0>,
                         cudaFuncAttributeMaxDynamicSharedMemorySize, GSMEM_BYTES);
    cudaFuncSetAttribute(bf16_gemm_bias<0, 1>,
                         cudaFuncAttributeMaxDynamicSharedMemorySize, GSMEM_BYTES);
    cudaFuncSetAttribute(bf16_gemm_bias<1, 1>,
                         cudaFuncAttributeMaxDynamicSharedMemorySize, GSMEM_BYTES);

    dim3 fgrid(SEQ / 128, NHEAD, BATCH), blk(256);

    // ---- self-attention block ----
    conv_f2bf(tgt, A0, NMM);
    conv_f2bf(sa_wq, w16, NW);
    launch_gemm16_bf16out(A0, w16, sa_bq, q16, MTOK, DMODEL, DMODEL);
    conv_f2bf(sa_wk, w16, NW);
    launch_gemm16_bf16out(A0, w16, sa_bk, k16, MTOK, DMODEL, DMODEL);
    conv_f2bf(sa_wv, w16, NW);
    launch_gemm16_bf16out(A0, w16, sa_bv, v16, MTOK, DMODEL, DMODEL);
    flash_attn_bf16<<<fgrid, blk, HSMEM_BYTES>>>(q16, k16, v16, A1, SEQ, SEQ);
    conv_f2bf(sa_wo, w16, NW);
    launch_gemm16(A1, w16, sa_bo, t, MTOK, DMODEL, DMODEL);
    add_ln_kernel<<<MTOK, blk>>>(tgt, t, ln1_g, ln1_b, x1, A0);

    // ---- cross-attention block ----
    conv_f2bf(ca_wq, w16, NW);
    launch_gemm16_bf16out(A0, w16, ca_bq, q16, MTOK, DMODEL, DMODEL);
    conv_f2bf(src, A1, NMM);
    conv_f2bf(ca_wk, w16, NW);
    launch_gemm16_bf16out(A1, w16, ca_bk, k16, MTOK, DMODEL, DMODEL);
    conv_f2bf(ca_wv, w16, NW);
    launch_gemm16_bf16out(A1, w16, ca_bv, v16, MTOK, DMODEL, DMODEL);
    flash_attn_bf16<<<fgrid, blk, HSMEM_BYTES>>>(q16, k16, v16, A1, SEQ, SEQ);
    conv_f2bf(ca_wo, w16, NW);
    launch_gemm16(A1, w16, ca_bo, t, MTOK, DMODEL, DMODEL);
    add_ln_kernel<<<MTOK, blk>>>(x1, t, ln2_g, ln2_b, x2, A0);

    // ---- feed-forward block ----
    conv_f2bf(ff_w1, w16, DMODEL * DFF);
    launch_gemm16_relu_bf16out(A0, w16, ff_b1, h16, MTOK, DFF, DMODEL);
    conv_f2bf(ff_w2, w16, DFF * DMODEL);
    launch_gemm16(h16, w16, ff_b2, t, MTOK, DMODEL, DFF);
    add_ln_kernel<<<MTOK, blk>>>(x2, t, ln3_g, ln3_b, out, nullptr);
}

// round 17
// speedup vs baseline: 1.0238x; 1.0238x over previous
#include <cuda_runtime.h>
#include <cuda_bf16.h>
#include <cstdint>
#include <mma.h>

using namespace nvcuda;

#define DMODEL 1024
#define NHEAD  16
#define DKH    64
#define DFF    4096
#define BATCH  4
#define SEQ    2048
#define MTOK   (BATCH * SEQ)

// ---------------- scratch (device globals; no allocation allowed) -------------
__device__ float g_x1[MTOK * DMODEL];
__device__ float g_x2[MTOK * DMODEL];
__device__ float g_t[MTOK * DMODEL];
__device__ __nv_bfloat16 g_q16[MTOK * DMODEL];
__device__ __nv_bfloat16 g_k16[MTOK * DMODEL];
__device__ __nv_bfloat16 g_v16[MTOK * DMODEL];
__device__ __nv_bfloat16 g_a16[2 * MTOK * DMODEL];  // two activation slots
__device__ __nv_bfloat16 g_h16[MTOK * DFF];         // FF hidden (bf16)
__device__ __nv_bfloat16 g_w16[DMODEL * DFF];       // weight scratch (8MB)

// ---------------- fp32 -> bf16 conversion ------------------------------------
__global__ __launch_bounds__(256) void f2bf_kernel(
    const float* __restrict__ in, __nv_bfloat16* __restrict__ out, int n4)
{
    int i = blockIdx.x * blockDim.x + threadIdx.x;
    if (i < n4) {
        float4 v = reinterpret_cast<const float4*>(in)[i];
        __nv_bfloat162 a = __floats2bfloat162_rn(v.x, v.y);
        __nv_bfloat162 b = __floats2bfloat162_rn(v.z, v.w);
        uint2 u;
        u.x = *reinterpret_cast<unsigned*>(&a);
        u.y = *reinterpret_cast<unsigned*>(&b);
        reinterpret_cast<uint2*>(out)[i] = u;
    }
}

// fp32 [K,1024] -> bf16 column block of concatenated [K, Ncat] weight buffer
__global__ __launch_bounds__(256) void f2bf_cat_kernel(
    const float* __restrict__ in, __nv_bfloat16* __restrict__ out,
    int Ncat, int coloff, int n4)
{
    int i = blockIdx.x * blockDim.x + threadIdx.x;
    if (i < n4) {
        int row = i >> 8;               // 1024 cols = 256 float4 per row
        int c4  = (i & 255) << 2;
        float4 v = reinterpret_cast<const float4*>(in)[i];
        __nv_bfloat162 a = __floats2bfloat162_rn(v.x, v.y);
        __nv_bfloat162 b = __floats2bfloat162_rn(v.z, v.w);
        uint2 u;
        u.x = *reinterpret_cast<unsigned*>(&a);
        u.y = *reinterpret_cast<unsigned*>(&b);
        *reinterpret_cast<uint2*>(out + (size_t)row * Ncat + coloff + c4) = u;
    }
}

// ---------------- cp.async helper ---------------------------------------------
__device__ __forceinline__ void cp16(void* dst, const void* src) {
    unsigned d = (unsigned)__cvta_generic_to_shared(dst);
    asm volatile("cp.async.cg.shared.global [%0], [%1], 16;\n" :: "r"(d), "l"(src));
}

// ---------------- bf16 WMMA GEMM (multi-output) --------------------------------
// BM=256, BN=128, BK=64; 8 warps, warp tile 64x64. 3-stage cp.async ring.
// Output columns are split into blocks of Nout; block i goes to C16_i / bias_i
// (bn is 128-aligned and Nout is a multiple of 128, so a CTA never straddles).
// OUT16=0: fp32 out to Cf (single output, Nout==N).  OUT16=1: bf16 out.
template <int RELU, int OUT16>
__global__ __launch_bounds__(256) void bf16_gemm_bias(
    const __nv_bfloat16* __restrict__ A, const __nv_bfloat16* __restrict__ W,
    const float* __restrict__ bias0, const float* __restrict__ bias1,
    const float* __restrict__ bias2,
    float* __restrict__ Cf,
    __nv_bfloat16* __restrict__ C16_0, __nv_bfloat16* __restrict__ C16_1,
    __nv_bfloat16* __restrict__ C16_2,
    int M, int N, int K, int Nout)
{
    constexpr int BM = 256, BN = 128, BK = 64;
    constexpr int LDA = 72;
    constexpr int LDB = 136;
    constexpr int ASTG = BM * LDA;
    constexpr int BSTG = BK * LDB;
    extern __shared__ __nv_bfloat16 gs[];
    __nv_bfloat16* const Asm = gs;
    __nv_bfloat16* const Bsm = gs + 3 * ASTG;

    const int tid = threadIdx.x;
    const int wid = tid >> 5;
    const int wm  = wid >> 1;
    const int wn  = wid & 1;
    const int bm  = blockIdx.y * BM;
    const int bn  = blockIdx.x * BN;

    const int blk = bn / Nout;
    const int cb  = bn % Nout;
    const float* const bias = (blk == 0) ? bias0 : (blk == 1) ? bias1 : bias2;
    __nv_bfloat16* const C16 = (blk == 0) ? C16_0 : (blk == 1) ? C16_1 : C16_2;

    wmma::fragment<wmma::accumulator, 16, 16, 16, float> acc[4][4];

    {
        float* fs = reinterpret_cast<float*>(gs);
        int rr = tid >> 5;
        int n4 = (tid & 31) << 2;
        float4 bv = *reinterpret_cast<const float4*>(bias + cb + n4);
        *reinterpret_cast<float4*>(&fs[rr * 136 + n4])       = bv;
        *reinterpret_cast<float4*>(&fs[(rr + 8) * 136 + n4]) = bv;
        __syncthreads();
        #pragma unroll
        for (int fc = 0; fc < 4; fc++) {
            wmma::load_matrix_sync(acc[0][fc], &fs[wn * 64 + fc * 16], 136,
                                   wmma::mem_row_major);
            #pragma unroll
            for (int fr = 1; fr < 4; fr++)
                #pragma unroll
                for (int e = 0; e < acc[0][fc].num_elements; e++)
                    acc[fr][fc].x[e] = acc[0][fc].x[e];
        }
        __syncthreads();
    }

    const __nv_bfloat16* const Ab = A + (size_t)bm * K;
    const __nv_bfloat16* const Wb = W + bn;

#define GISS(st, k0)                                                             \
    do {                                                                         \
        __nv_bfloat16* as = Asm + (st) * ASTG;                                   \
        __nv_bfloat16* bs = Bsm + (st) * BSTG;                                   \
        _Pragma("unroll")                                                        \
        for (int i = 0; i < 8; i++) {                                            \
            int idx = tid + i * 256;                                             \
            int r = idx >> 3, c8 = (idx & 7) * 8;                                \
            cp16(&as[r * LDA + c8], Ab + (size_t)r * K + (k0) + c8);             \
        }                                                                        \
        _Pragma("unroll")                                                        \
        for (int i = 0; i < 4; i++) {                                            \
            int idx = tid + i * 256;                                             \
            int r = idx >> 4, c8 = (idx & 15) * 8;                               \
            cp16(&bs[r * LDB + c8], Wb + (size_t)((k0) + r) * N + c8);           \
        }                                                                        \
        asm volatile("cp.async.commit_group;\n");                                \
    } while (0)

    const int NS = K / BK;
    GISS(0, 0);
    if (NS > 1) GISS(1, BK);

    int st = 0;
    for (int s = 0; s < NS; s++) {
        if (s + 1 < NS) asm volatile("cp.async.wait_group 1;\n");
        else            asm volatile("cp.async.wait_group 0;\n");
        __syncthreads();

        const __nv_bfloat16* as = Asm + st * ASTG;
        const __nv_bfloat16* bs = Bsm + st * BSTG;
        #pragma unroll
        for (int kk = 0; kk < BK; kk += 16) {
            wmma::fragment<wmma::matrix_a, 16, 16, 16, __nv_bfloat16,
                           wmma::row_major> af[4];
            wmma::fragment<wmma::matrix_b, 16, 16, 16, __nv_bfloat16,
                           wmma::row_major> bf[4];
            #pragma unroll
            for (int fr = 0; fr < 4; fr++)
                wmma::load_matrix_sync(af[fr], &as[(wm * 64 + fr * 16) * LDA + kk], LDA);
            #pragma unroll
            for (int fc = 0; fc < 4; fc++)
                wmma::load_matrix_sync(bf[fc], &bs[kk * LDB + wn * 64 + fc * 16], LDB);
            #pragma unroll
            for (int fr = 0; fr < 4; fr++)
                #pragma unroll
                for (int fc = 0; fc < 4; fc++)
                    wmma::mma_sync(acc[fr][fc], af[fr], bf[fc], acc[fr][fc]);
        }

        if (s + 2 < NS) {
            int nst = (st + 2) % 3;
            GISS(nst, (s + 2) * BK);
        }
        st = (st + 1) % 3;
    }
#undef GISS

    if (OUT16) {
        __syncthreads();
        float* stg = reinterpret_cast<float*>(gs) + wid * 256;
        const int lane = tid & 31;
        const int row  = lane >> 1;
        const int col  = (lane & 1) * 8;
        #pragma unroll
        for (int fr = 0; fr < 4; fr++)
            #pragma unroll
            for (int fc = 0; fc < 4; fc++) {
                if (RELU) {
                    #pragma unroll
                    for (int e = 0; e < acc[fr][fc].num_elements; e++)
                        acc[fr][fc].x[e] = fmaxf(acc[fr][fc].x[e], 0.0f);
                }
                wmma::store_matrix_sync(stg, acc[fr][fc], 16, wmma::mem_row_major);
                __syncwarp();
                float4 a  = *reinterpret_cast<float4*>(&stg[row * 16 + col]);
                float4 b4 = *reinterpret_cast<float4*>(&stg[row * 16 + col + 4]);
                __nv_bfloat162 p0 = __floats2bfloat162_rn(a.x,  a.y);
                __nv_bfloat162 p1 = __floats2bfloat162_rn(a.z,  a.w);
                __nv_bfloat162 p2 = __floats2bfloat162_rn(b4.x, b4.y);
                __nv_bfloat162 p3 = __floats2bfloat162_rn(b4.z, b4.w);
                uint4 u;
                u.x = *reinterpret_cast<unsigned*>(&p0);
                u.y = *reinterpret_cast<unsigned*>(&p1);
                u.z = *reinterpret_cast<unsigned*>(&p2);
                u.w = *reinterpret_cast<unsigned*>(&p3);
                *reinterpret_cast<uint4*>(
                    C16 + (size_t)(bm + wm * 64 + fr * 16 + row) * Nout
                        + cb + wn * 64 + fc * 16 + col) = u;
                __syncwarp();
            }
    } else {
        #pragma unroll
        for (int fr = 0; fr < 4; fr++)
            #pragma unroll
            for (int fc = 0; fc < 4; fc++) {
                if (RELU) {
                    #pragma unroll
                    for (int e = 0; e < acc[fr][fc].num_elements; e++)
                        acc[fr][fc].x[e] = fmaxf(acc[fr][fc].x[e], 0.0f);
                }
                float* cp = Cf + (size_t)(bm + wm * 64 + fr * 16) * Nout
                               + cb + wn * 64 + fc * 16;
                wmma::store_matrix_sync(cp, acc[fr][fc], Nout, wmma::mem_row_major);
            }
    }
}

#define GSMEM_BYTES ((3 * (256 * 72) + 3 * (64 * 136)) * 2)   // 162816

// ============== bf16 tensor-core flash attention (m16n8k16, dk=64) ============
// (R15 proven version: KV tile 64)
#define HLDK 72
#define HLDV 72
#define HLDP 72
#define HKSTG (64 * HLDK)
#define HVT_OFF (2 * HKSTG)
#define HVSTG (64 * HLDV)
#define HPS_OFF (HVT_OFF + 2 * HVSTG)
#define HSMEM_H (HPS_OFF + 128 * HLDP)
#define HSMEM_BYTES (HSMEM_H * 2)

__device__ __forceinline__ void mma_bf16(float* d, const unsigned* a,
                                         const unsigned* b) {
    asm volatile(
        "mma.sync.aligned.m16n8k16.row.col.f32.bf16.bf16.f32 "
        "{%0,%1,%2,%3}, {%4,%5,%6,%7}, {%8,%9}, {%0,%1,%2,%3};\n"
        : "+f"(d[0]), "+f"(d[1]), "+f"(d[2]), "+f"(d[3])
        : "r"(a[0]), "r"(a[1]), "r"(a[2]), "r"(a[3]), "r"(b[0]), "r"(b[1]));
}

__global__ __launch_bounds__(256) void flash_attn_bf16(
    const __nv_bfloat16* __restrict__ Qg, const __nv_bfloat16* __restrict__ Kg,
    const __nv_bfloat16* __restrict__ Vg, __nv_bfloat16* __restrict__ Og16,
    int Sq, int Skv)
{
    extern __shared__ __nv_bfloat16 hsm[];
    unsigned* smw = reinterpret_cast<unsigned*>(hsm);

    const int tid  = threadIdx.x;
    const int lane = tid & 31;
    const int w    = tid >> 5;
    const int q0   = blockIdx.x * 128;
    const int h    = blockIdx.y;
    const int b    = blockIdx.z;
    const int r0   = lane >> 2;
    const int cq   = lane & 3;

    const int kc0 = tid, kc1 = tid + 256;
#define KISS(st, kvoff)                                                          \
    do {                                                                         \
        __nv_bfloat16* kb = hsm + (st) * HKSTG;                                  \
        { int r = kc0 >> 3, o8 = (kc0 & 7) * 8;                                  \
          cp16(&kb[r * HLDK + o8],                                               \
               Kg + (size_t)(b * Skv + (kvoff) + r) * DMODEL + h * DKH + o8); }  \
        { int r = kc1 >> 3, o8 = (kc1 & 7) * 8;                                  \
          cp16(&kb[r * HLDK + o8],                                               \
               Kg + (size_t)(b * Skv + (kvoff) + r) * DMODEL + h * DKH + o8); }  \
        asm volatile("cp.async.commit_group;\n");                                \
    } while (0)

    const int vc = tid & 63;
    const int vd = (tid >> 6) * 16;
    uint4 vr0, vr1;
#define VLOAD(kvoff)                                                             \
    do {                                                                         \
        const uint4* vp = reinterpret_cast<const uint4*>(                        \
            Vg + (size_t)(b * Skv + (kvoff) + vc) * DMODEL + h * DKH + vd);      \
        vr0 = vp[0]; vr1 = vp[1];                                                \
    } while (0)

    KISS(0, 0);
    VLOAD(0);

    unsigned qa[4][4];
    {
        const __nv_bfloat162 s2 = __float2bfloat162_rn(0.125f);
        const __nv_bfloat16* Qb = Qg + (size_t)(b * Sq + q0 + w * 16) * DMODEL + h * DKH;
        #pragma unroll
        for (int ds = 0; ds < 4; ds++) {
            #pragma unroll
            for (int p = 0; p < 4; p++) {
                int rr = (p & 1) ? r0 + 8 : r0;
                int cc = ds * 16 + 2 * cq + ((p & 2) ? 8 : 0);
                __nv_bfloat162 x = *reinterpret_cast<const __nv_bfloat162*>(
                    Qb + (size_t)rr * DMODEL + cc);
                x = __hmul2(x, s2);
                qa[ds][p] = *reinterpret_cast<unsigned*>(&x);
            }
        }
    }

    float m0 = -1e30f, m1 = -1e30f, l0 = 0.0f, l1 = 0.0f;
    float o[8][4];
    #pragma unroll
    for (int nt = 0; nt < 8; nt++)
        o[nt][0] = o[nt][1] = o[nt][2] = o[nt][3] = 0.0f;

    unsigned* const pw = smw + (HPS_OFF >> 1) + (w * 16) * (HLDP >> 1);
    const int NS = Skv / 64;

    for (int s = 0; s < NS; s++) {
        {
            __nv_bfloat16* vt = hsm + HVT_OFF + (s & 1) * HVSTG;
            __nv_bfloat16 tmp[16];
            *reinterpret_cast<uint4*>(tmp)     = vr0;
            *reinterpret_cast<uint4*>(tmp + 8) = vr1;
            #pragma unroll
            for (int j = 0; j < 16; j++)
                vt[(vd + j) * HLDV + vc] = tmp[j];
        }
        if (s + 1 < NS) {
            __syncthreads();
            KISS((s + 1) & 1, (s + 1) * 64);
            VLOAD((s + 1) * 64);
            asm volatile("cp.async.wait_group 1;\n");
        } else {
            asm volatile("cp.async.wait_group 0;\n");
        }
        __syncthreads();

        const unsigned* kw  = smw + (((s & 1) * HKSTG) >> 1);
        const unsigned* vtw = smw + ((HVT_OFF + (s & 1) * HVSTG) >> 1);

        float sc[8][4];
        #pragma unroll
        for (int nt = 0; nt < 8; nt++)
            sc[nt][0] = sc[nt][1] = sc[nt][2] = sc[nt][3] = 0.0f;

        #pragma unroll
        for (int ds = 0; ds < 4; ds++) {
            #pragma unroll
            for (int nt = 0; nt < 8; nt++) {
                const unsigned* kp = kw + (nt * 8 + r0) * 36 + ds * 8 + cq;
                unsigned bb[2] = { kp[0], kp[4] };
                mma_bf16(sc[nt], qa[ds], bb);
            }
        }

        float mx0 = sc[0][0], mx1 = sc[0][2];
        #pragma unroll
        for (int nt = 0; nt < 8; nt++) {
            mx0 = fmaxf(mx0, fmaxf(sc[nt][0], sc[nt][1]));
            mx1 = fmaxf(mx1, fmaxf(sc[nt][2], sc[nt][3]));
        }
        mx0 = fmaxf(mx0, __shfl_xor_sync(0xffffffffu, mx0, 1));
        mx0 = fmaxf(mx0, __shfl_xor_sync(0xffffffffu, mx0, 2));
        mx1 = fmaxf(mx1, __shfl_xor_sync(0xffffffffu, mx1, 1));
        mx1 = fmaxf(mx1, __shfl_xor_sync(0xffffffffu, mx1, 2));

        float mn0 = fmaxf(m0, mx0), mn1 = fmaxf(m1, mx1);
        float al0 = __expf(m0 - mn0), al1 = __expf(m1 - mn1);
        m0 = mn0; m1 = mn1;

        float sum0 = 0.0f, sum1 = 0.0f;
        #pragma unroll
        for (int nt = 0; nt < 8; nt++) {
            sc[nt][0] = __expf(sc[nt][0] - mn0);
            sc[nt][1] = __expf(sc[nt][1] - mn0);
            sc[nt][2] = __expf(sc[nt][2] - mn1);
            sc[nt][3] = __expf(sc[nt][3] - mn1);
            sum0 += sc[nt][0] + sc[nt][1];
            sum1 += sc[nt][2] + sc[nt][3];
        }
        sum0 += __shfl_xor_sync(0xffffffffu, sum0, 1);
        sum0 += __shfl_xor_sync(0xffffffffu, sum0, 2);
        sum1 += __shfl_xor_sync(0xffffffffu, sum1, 1);
        sum1 += __shfl_xor_sync(0xffffffffu, sum1, 2);
        l0 = l0 * al0 + sum0;
        l1 = l1 * al1 + sum1;

        #pragma unroll
        for (int nt = 0; nt < 8; nt++) {
            o[nt][0] *= al0; o[nt][1] *= al0;
            o[nt][2] *= al1; o[nt][3] *= al1;
            __nv_bfloat162 p01 = __floats2bfloat162_rn(sc[nt][0], sc[nt][1]);
            __nv_bfloat162 p23 = __floats2bfloat162_rn(sc[nt][2], sc[nt][3]);
            pw[r0 * 36 + nt * 4 + cq]       = *reinterpret_cast<unsigned*>(&p01);
            pw[(r0 + 8) * 36 + nt * 4 + cq] = *reinterpret_cast<unsigned*>(&p23);
        }
        __syncwarp();

        #pragma unroll
        for (int kk = 0; kk < 4; kk++) {
            unsigned pa[4];
            pa[0] = pw[r0 * 36 + kk * 8 + cq];
            pa[1] = pw[(r0 + 8) * 36 + kk * 8 + cq];
            pa[2] = pw[r0 * 36 + kk * 8 + cq + 4];
            pa[3] = pw[(r0 + 8) * 36 + kk * 8 + cq + 4];
            #pragma unroll
            for (int nt = 0; nt < 8; nt++) {
                const unsigned* vp = vtw + (nt * 8 + r0) * 36 + kk * 8 + cq;
                unsigned bb[2] = { vp[0], vp[4] };
                mma_bf16(o[nt], pa, bb);
            }
        }
    }
#undef KISS
#undef VLOAD

    const float i0 = 1.0f / l0, i1 = 1.0f / l1;
    __nv_bfloat16* Ob = Og16 + (size_t)(b * Sq + q0 + w * 16) * DMODEL + h * DKH;
    #pragma unroll
    for (int nt = 0; nt < 8; nt++) {
        __nv_bfloat162 v0 = __floats2bfloat162_rn(o[nt][0] * i0, o[nt][1] * i0);
        __nv_bfloat162 v1 = __floats2bfloat162_rn(o[nt][2] * i1, o[nt][3] * i1);
        *reinterpret_cast<unsigned*>(Ob + (size_t)r0 * DMODEL + nt * 8 + 2 * cq) =
            *reinterpret_cast<unsigned*>(&v0);
        *reinterpret_cast<unsigned*>(Ob + (size_t)(r0 + 8) * DMODEL + nt * 8 + 2 * cq) =
            *reinterpret_cast<unsigned*>(&v1);
    }
}

// ---------------- out = LayerNorm(a + c) * g + b  (+ optional bf16 copy) ------
__global__ __launch_bounds__(256) void add_ln_kernel(
    const float* __restrict__ a, const float* __restrict__ cadd,
    const float* __restrict__ g, const float* __restrict__ be,
    float* __restrict__ out, __nv_bfloat16* __restrict__ out16)
{
    __shared__ float red[16];
    const int row = blockIdx.x;
    const int tid = threadIdx.x;
    const size_t base = (size_t)row * DMODEL + tid * 4;

    float4 av = *reinterpret_cast<const float4*>(a + base);
    float4 cv = *reinterpret_cast<const float4*>(cadd + base);
    float x0 = av.x + cv.x, x1 = av.y + cv.y;
    float x2 = av.z + cv.z, x3 = av.w + cv.w;

    float s  = x0 + x1 + x2 + x3;
    float ss = x0 * x0 + x1 * x1 + x2 * x2 + x3 * x3;
    #pragma unroll
    for (int off = 16; off; off >>= 1) {
        s  += __shfl_xor_sync(0xffffffffu, s,  off);
        ss += __shfl_xor_sync(0xffffffffu, ss, off);
    }
    if ((tid & 31) == 0) { red[tid >> 5] = s; red[8 + (tid >> 5)] = ss; }
    __syncthreads();
    float ts = 0.0f, tss = 0.0f;
    #pragma unroll
    for (int i = 0; i < 8; i++) { ts += red[i]; tss += red[8 + i]; }

    const float mu  = ts * (1.0f / DMODEL);
    const float var = tss * (1.0f / DMODEL) - mu * mu;
    const float inv = rsqrtf(var + 1e-5f);

    float4 gv = *reinterpret_cast<const float4*>(g  + tid * 4);
    float4 bv = *reinterpret_cast<const float4*>(be + tid * 4);
    float4 ov;
    ov.x = (x0 - mu) * inv * gv.x + bv.x;
    ov.y = (x1 - mu) * inv * gv.y + bv.y;
    ov.z = (x2 - mu) * inv * gv.z + bv.z;
    ov.w = (x3 - mu) * inv * gv.w + bv.w;
    *reinterpret_cast<float4*>(out + base) = ov;

    if (out16) {
        __nv_bfloat162 p0 = __floats2bfloat162_rn(ov.x, ov.y);
        __nv_bfloat162 p1 = __floats2bfloat162_rn(ov.z, ov.w);
        uint2 u;
        u.x = *reinterpret_cast<unsigned*>(&p0);
        u.y = *reinterpret_cast<unsigned*>(&p1);
        *reinterpret_cast<uint2*>(out16 + base) = u;
    }
}

// ------------------------------- host driver ----------------------------------
static inline void conv_f2bf(const float* in, __nv_bfloat16* out, int n) {
    int n4 = n >> 2;
    f2bf_kernel<<<(n4 + 255) / 256, 256>>>(in, out, n4);
}

static inline void conv_cat(const float* in, __nv_bfloat16* out,
                            int Ncat, int coloff) {
    int n4 = (DMODEL * DMODEL) >> 2;
    f2bf_cat_kernel<<<(n4 + 255) / 256, 256>>>(in, out, Ncat, coloff, n4);
}

static inline void launch_gemm_f32(const __nv_bfloat16* A, const __nv_bfloat16* W,
                                   const float* B, float* Cf, int M, int N, int K)
{
    dim3 grid(N / 128, M / 256), blk(256);
    bf16_gemm_bias<0, 0><<<grid, blk, GSMEM_BYTES>>>(
        A, W, B, B, B, Cf, nullptr, nullptr, nullptr, M, N, K, N);
}

static inline void launch_gemm_bf16(const __nv_bfloat16* A, const __nv_bfloat16* W,
                                    const float* b0, const float* b1, const float* b2,
                                    __nv_bfloat16* c0, __nv_bfloat16* c1,
                                    __nv_bfloat16* c2,
                                    int M, int N, int K, int Nout)
{
    dim3 grid(N / 128, M / 256), blk(256);
    bf16_gemm_bias<0, 1><<<grid, blk, GSMEM_BYTES>>>(
        A, W, b0, b1, b2, nullptr, c0, c1, c2, M, N, K, Nout);
}

static inline void launch_gemm_relu_bf16(const __nv_bfloat16* A,
                                         const __nv_bfloat16* W, const float* B,
                                         __nv_bfloat16* C16, int M, int N, int K)
{
    dim3 grid(N / 128, M / 256), blk(256);
    bf16_gemm_bias<1, 1><<<grid, blk, GSMEM_BYTES>>>(
        A, W, B, B, B, nullptr, C16, C16, C16, M, N, K, N);
}

extern "C" void kernel_launch(void* const* d_in, const int* in_sizes, int n_in,
                              void* d_out, int out_size)
{
    const float* src   = (const float*)d_in[0];
    const float* tgt   = (const float*)d_in[1];
    const float* sa_wq = (const float*)d_in[2];
    const float* sa_bq = (const float*)d_in[3];
    const float* sa_wk = (const float*)d_in[4];
    const float* sa_bk = (const float*)d_in[5];
    const float* sa_wv = (const float*)d_in[6];
    const float* sa_bv = (const float*)d_in[7];
    const float* sa_wo = (const float*)d_in[8];
    const float* sa_bo = (const float*)d_in[9];
    const float* ca_wq = (const float*)d_in[10];
    const float* ca_bq = (const float*)d_in[11];
    const float* ca_wk = (const float*)d_in[12];
    const float* ca_bk = (const float*)d_in[13];
    const float* ca_wv = (const float*)d_in[14];
    const float* ca_bv = (const float*)d_in[15];
    const float* ca_wo = (const float*)d_in[16];
    const float* ca_bo = (const float*)d_in[17];
    const float* ff_w1 = (const float*)d_in[18];
    const float* ff_b1 = (const float*)d_in[19];
    const float* ff_w2 = (const float*)d_in[20];
    const float* ff_b2 = (const float*)d_in[21];
    const float* ln1_g = (const float*)d_in[22];
    const float* ln1_b = (const float*)d_in[23];
    const float* ln2_g = (const float*)d_in[24];
    const float* ln2_b = (const float*)d_in[25];
    const float* ln3_g = (const float*)d_in[26];
    const float* ln3_b = (const float*)d_in[27];
    float* out = (float*)d_out;

    float *x1, *x2, *t;
    __nv_bfloat16 *q16, *k16, *v16, *a16, *h16, *w16;
    cudaGetSymbolAddress((void**)&x1,  g_x1);
    cudaGetSymbolAddress((void**)&x2,  g_x2);
    cudaGetSymbolAddress((void**)&t,   g_t);
    cudaGetSymbolAddress((void**)&q16, g_q16);
    cudaGetSymbolAddress((void**)&k16, g_k16);
    cudaGetSymbolAddress((void**)&v16, g_v16);
    cudaGetSymbolAddress((void**)&a16, g_a16);
    cudaGetSymbolAddress((void**)&h16, g_h16);
    cudaGetSymbolAddress((void**)&w16, g_w16);

    const int NMM = MTOK * DMODEL;
    const int NW  = DMODEL * DMODEL;
    __nv_bfloat16* A0 = a16;
    __nv_bfloat16* A1 = a16 + NMM;

    cudaFuncSetAttribute(flash_attn_bf16,
                         cudaFuncAttributeMaxDynamicSharedMemorySize, HSMEM_BYTES);
    cudaFuncSetAttribute(bf16_gemm_bias<0, 0>,
                         cudaFuncAttributeMaxDynamicSharedMemorySize, GSMEM_BYTES);
    cudaFuncSetAttribute(bf16_gemm_bias<0, 1>,
                         cudaFuncAttributeMaxDynamicSharedMemorySize, GSMEM_BYTES);
    cudaFuncSetAttribute(bf16_gemm_bias<1, 1>,
                         cudaFuncAttributeMaxDynamicSharedMemorySize, GSMEM_BYTES);

    dim3 fgrid(SEQ / 128, NHEAD, BATCH), blk(256);

    // ---- self-attention block: fused QKV projection ----
    conv_f2bf(tgt, A0, NMM);
    conv_cat(sa_wq, w16, 3 * DMODEL, 0);
    conv_cat(sa_wk, w16, 3 * DMODEL, DMODEL);
    conv_cat(sa_wv, w16, 3 * DMODEL, 2 * DMODEL);
    launch_gemm_bf16(A0, w16, sa_bq, sa_bk, sa_bv, q16, k16, v16,
                     MTOK, 3 * DMODEL, DMODEL, DMODEL);
    flash_attn_bf16<<<fgrid, blk, HSMEM_BYTES>>>(q16, k16, v16, A1, SEQ, SEQ);
    conv_f2bf(sa_wo, w16, NW);
    launch_gemm_f32(A1, w16, sa_bo, t, MTOK, DMODEL, DMODEL);
    add_ln_kernel<<<MTOK, blk>>>(tgt, t, ln1_g, ln1_b, x1, A0);

    // ---- cross-attention block: Q separate, fused KV on src ----
    conv_f2bf(ca_wq, w16, NW);
    launch_gemm_bf16(A0, w16, ca_bq, ca_bq, ca_bq, q16, q16, q16,
                     MTOK, DMODEL, DMODEL, DMODEL);
    conv_f2bf(src, A1, NMM);
    conv_cat(ca_wk, w16, 2 * DMODEL, 0);
    conv_cat(ca_wv, w16, 2 * DMODEL, DMODEL);
    launch_gemm_bf16(A1, w16, ca_bk, ca_bv, ca_bv, k16, v16, v16,
                     MTOK, 2 * DMODEL, DMODEL, DMODEL);
    flash_attn_bf16<<<fgrid, blk, HSMEM_BYTES>>>(q16, k16, v16, A1, SEQ, SEQ);
    conv_f2bf(ca_wo, w16, NW);
    launch_gemm_f32(A1, w16, ca_bo, t, MTOK, DMODEL, DMODEL);
    add_ln_kernel<<<MTOK, blk>>>(x1, t, ln2_g, ln2_b, x2, A0);

    // ---- feed-forward block ----
    conv_f2bf(ff_w1, w16, DMODEL * DFF);
    launch_gemm_relu_bf16(A0, w16, ff_b1, h16, MTOK, DFF, DMODEL);
    conv_f2bf(ff_w2, w16, DFF * DMODEL);
    launch_gemm_f32(h16, w16, ff_b2, t, MTOK, DMODEL, DFF);
    add_ln_kernel<<<MTOK, blk>>>(x2, t, ln3_g, ln3_b, out, nullptr);
}